// round 13
// baseline (speedup 1.0000x reference)
#include <cuda_runtime.h>
#include <math_constants.h>
#include <cstdint>

// VQ-VAE vector quantizer, GB300 (PTX sm_103). Round 13: DP4A screening with
// register-resident masks and NO x[64] register array (refinement/epilogue
// reload x from L1-hot global) -> kill the reg-clamp spills seen in R7/R12.
// inputs:  d_in[0] = inputs [64,64,32,32] fp32 NCHW, d_in[1] = emb_w [512,64] fp32
// output:  d_out fp32: loss[1] | out[4194304] NCHW | idx[65536]

#define DD        64
#define KK        512
#define NPIX      65536
#define BLOCK     512
#define GRID      128
#define OUT_ELEMS (NPIX * DD)

#define OFF_E    0                      // int8 codebook [512][64] = 32768 B
#define OFF_B    32768                  // [512] f32 ||e||^2
#define OFF_SCR  34816                  // 64 f32 scratch
#define SMEM_TOTAL (OFF_SCR + 64 * 4)   // 35072 B

__device__ float g_part[GRID];
__device__ unsigned int g_cnt;          // zero-init; restored to 0 each run

__global__ __launch_bounds__(BLOCK, 1)
void vq_main(const float* __restrict__ in, const float* __restrict__ emb,
             float* __restrict__ out) {
    extern __shared__ char smem[];
    uint4* Ecb = (uint4*)(smem + OFF_E);
    float* sB  = (float*)(smem + OFF_B);
    float* scr = (float*)(smem + OFF_SCR);
    const int tid = threadIdx.x, wid = tid >> 5, lane = tid & 31;

    // ---- codebook prologue: thread t owns code t (BLOCK == KK) ----
    const float* er = emb + tid * DD;
    float Bk = 0.0f, L1e = 0.0f, mxe = 0.0f;
    #pragma unroll 8
    for (int d = 0; d < DD; d++) {
        float v = er[d];
        Bk = __fadd_rn(Bk, __fmul_rn(v, v));    // R1/R2-proven exact order
        float a = fabsf(v);
        L1e += a;
        mxe = fmaxf(mxe, a);
    }
    sB[tid] = Bk;
    float m1 = mxe, m2 = L1e;
    #pragma unroll
    for (int o = 16; o > 0; o >>= 1) {
        m1 = fmaxf(m1, __shfl_xor_sync(~0u, m1, o));
        m2 = fmaxf(m2, __shfl_xor_sync(~0u, m2, o));
    }
    if (lane == 0) { scr[wid] = m1; scr[16 + wid] = m2; }
    __syncthreads();
    float maxe = scr[0], L1emax = scr[16];
    #pragma unroll
    for (int w = 1; w < 16; w++) {
        maxe   = fmaxf(maxe,   scr[w]);
        L1emax = fmaxf(L1emax, scr[16 + w]);
    }
    maxe = fmaxf(maxe, 1e-30f);
    const float se = maxe * (1.0f / 127.0f);
    const float inv_se = 127.0f / maxe;
    {   // quantize + pack own code row: [64] int8 -> 16 u32
        uint32_t* Erow = (uint32_t*)(Ecb + tid * 4);
        #pragma unroll
        for (int i = 0; i < 16; i++) {
            int q0 = __float2int_rn(er[4 * i + 0] * inv_se);
            int q1 = __float2int_rn(er[4 * i + 1] * inv_se);
            int q2 = __float2int_rn(er[4 * i + 2] * inv_se);
            int q3 = __float2int_rn(er[4 * i + 3] * inv_se);
            Erow[i] = (uint32_t)(q0 & 0xFF) | ((uint32_t)(q1 & 0xFF) << 8) |
                      ((uint32_t)(q2 & 0xFF) << 16) | ((uint32_t)(q3 & 0xFF) << 24);
        }
    }
    __syncthreads();

    // ---- pixel stats (A in the proven R1 order, L1, max) ----
    const int n  = blockIdx.x * BLOCK + tid;
    const int b  = n >> 10;
    const int hw = n & 1023;
    const float* px = in + (size_t)b * 65536 + hw;

    float a0 = 0.f, a1 = 0.f, a2 = 0.f, a3 = 0.f, L1x = 0.f, mxx = 0.f;
    #pragma unroll
    for (int d = 0; d < DD; d += 4) {
        float v0 = px[(size_t)(d + 0) << 10];
        float v1 = px[(size_t)(d + 1) << 10];
        float v2 = px[(size_t)(d + 2) << 10];
        float v3 = px[(size_t)(d + 3) << 10];
        a0 = __fadd_rn(a0, __fmul_rn(v0, v0));
        a1 = __fadd_rn(a1, __fmul_rn(v1, v1));
        a2 = __fadd_rn(a2, __fmul_rn(v2, v2));
        a3 = __fadd_rn(a3, __fmul_rn(v3, v3));
        L1x += fabsf(v0) + fabsf(v1) + fabsf(v2) + fabsf(v3);
        mxx = fmaxf(mxx, fmaxf(fmaxf(fabsf(v0), fabsf(v1)),
                               fmaxf(fabsf(v2), fabsf(v3))));
    }
    const float A = __fadd_rn(__fadd_rn(a0, a2), __fadd_rn(a1, a3));
    mxx = fmaxf(mxx, 1e-30f);
    const float sx = mxx * (1.0f / 127.0f);
    const float inv_sx = 127.0f / mxx;

    uint32_t X[16];
    #pragma unroll
    for (int i = 0; i < 16; i++) {
        int q0 = __float2int_rn(px[(size_t)(4 * i + 0) << 10] * inv_sx);
        int q1 = __float2int_rn(px[(size_t)(4 * i + 1) << 10] * inv_sx);
        int q2 = __float2int_rn(px[(size_t)(4 * i + 2) << 10] * inv_sx);
        int q3 = __float2int_rn(px[(size_t)(4 * i + 3) << 10] * inv_sx);
        X[i] = (uint32_t)(q0 & 0xFF) | ((uint32_t)(q1 & 0xFF) << 8) |
               ((uint32_t)(q2 & 0xFF) << 16) | ((uint32_t)(q3 & 0xFF) << 24);
    }
    const float c2 = -2.0f * sx * se;
    const float margin = sx * L1emax + se * L1x + 16.0f * sx * se + 1e-6f; // 2*delta

    // ---- DP4A screening: masks in registers, dual 8-chains per code ----
    float thr = CUDART_INF_F;
    uint32_t cm[16];
    #pragma unroll 1
    for (int w = 0; w < 16; w++) {
        uint32_t m = 0;
        const uint4* ep = Ecb + (w * 32) * 4;
        const float* bp = sB + w * 32;
        #pragma unroll 2
        for (int j = 0; j < 32; j++) {
            uint4 qa = ep[4 * j + 0];
            uint4 qb = ep[4 * j + 1];
            int Pa = 0, Pb = 0;
            Pa = __dp4a((int)X[0],  (int)qa.x, Pa);
            Pa = __dp4a((int)X[1],  (int)qa.y, Pa);
            Pa = __dp4a((int)X[2],  (int)qa.z, Pa);
            Pa = __dp4a((int)X[3],  (int)qa.w, Pa);
            Pa = __dp4a((int)X[4],  (int)qb.x, Pa);
            Pa = __dp4a((int)X[5],  (int)qb.y, Pa);
            Pa = __dp4a((int)X[6],  (int)qb.z, Pa);
            Pa = __dp4a((int)X[7],  (int)qb.w, Pa);
            uint4 qc = ep[4 * j + 2];
            uint4 qd = ep[4 * j + 3];
            Pb = __dp4a((int)X[8],  (int)qc.x, Pb);
            Pb = __dp4a((int)X[9],  (int)qc.y, Pb);
            Pb = __dp4a((int)X[10], (int)qc.z, Pb);
            Pb = __dp4a((int)X[11], (int)qc.w, Pb);
            Pb = __dp4a((int)X[12], (int)qd.x, Pb);
            Pb = __dp4a((int)X[13], (int)qd.y, Pb);
            Pb = __dp4a((int)X[14], (int)qd.z, Pb);
            Pb = __dp4a((int)X[15], (int)qd.w, Pb);
            float s = fmaf(c2, (float)(Pa + Pb), bp[j]);
            m = (m >> 1) | ((s <= thr) ? 0x80000000u : 0u);  // bit j after 32
            thr = fminf(thr, __fadd_rn(s, margin));
        }
        cm[w] = m;
    }

    // ---- exact refinement (bit-matches R2): ascending k, strict '<';
    //      x reloaded from global (L1-hot), no x[64] register array ----
    float best = CUDART_INF_F;
    int bi = 0;
    #pragma unroll
    for (int w = 0; w < 16; w++) {
        uint32_t m = cm[w];
        while (m) {
            int j = __ffs(m) - 1;
            m &= m - 1;
            int kk = w * 32 + j;
            const float4* e4p = (const float4*)(emb + kk * DD);
            float p = 0.0f;
            #pragma unroll
            for (int q = 0; q < DD / 4; q++) {
                float4 e4 = e4p[q];
                p = fmaf(e4.x, px[(size_t)(4 * q + 0) << 10], p);
                p = fmaf(e4.y, px[(size_t)(4 * q + 1) << 10], p);
                p = fmaf(e4.z, px[(size_t)(4 * q + 2) << 10], p);
                p = fmaf(e4.w, px[(size_t)(4 * q + 3) << 10], p);
            }
            float dist = __fsub_rn(__fadd_rn(A, sB[kk]), __fmul_rn(2.0f, p));
            if (dist < best) { best = dist; bi = kk; }
        }
    }

    // ---- epilogue (bit-matches R2): stream x from global ----
    float* pout = out + 1 + (size_t)b * 65536 + hw;
    const float* qr = emb + bi * DD;
    float sq = 0.0f;
    #pragma unroll 8
    for (int d = 0; d < DD; d++) {
        float xd   = px[(size_t)d << 10];
        float qd   = qr[d];
        float diff = __fsub_rn(qd, xd);
        sq = fmaf(diff, diff, sq);
        pout[(size_t)d << 10] = __fadd_rn(xd, diff);
    }
    out[1 + (size_t)OUT_ELEMS + n] = (float)bi;

    // ---- loss: block reduce -> per-CTA partial; last CTA finalizes ----
    __syncthreads();
    #pragma unroll
    for (int o = 16; o > 0; o >>= 1)
        sq += __shfl_down_sync(~0u, sq, o);
    if (lane == 0) scr[wid] = sq;
    __syncthreads();
    if (tid == 0) {
        float s = 0.0f;
        #pragma unroll
        for (int w = 0; w < 16; w++) s += scr[w];
        g_part[blockIdx.x] = s;
        __threadfence();
        unsigned int prev = atomicAdd(&g_cnt, 1u);
        if (prev == GRID - 1) {
            float tot = 0.0f;
            volatile float* gp = g_part;
            #pragma unroll
            for (int i = 0; i < GRID; i++) tot += gp[i];
            float mmean = tot * (1.0f / (float)OUT_ELEMS);
            out[0] = __fadd_rn(mmean, __fmul_rn(0.25f, mmean));
            g_cnt = 0u;
        }
    }
}

extern "C" void kernel_launch(void* const* d_in, const int* in_sizes, int n_in,
                              void* d_out, int out_size) {
    (void)in_sizes; (void)n_in; (void)out_size;
    cudaFuncSetAttribute(vq_main, cudaFuncAttributeMaxDynamicSharedMemorySize,
                         SMEM_TOTAL);
    vq_main<<<GRID, BLOCK, SMEM_TOTAL>>>((const float*)d_in[0],
                                         (const float*)d_in[1], (float*)d_out);
}